// round 17
// baseline (speedup 1.0000x reference)
#include <cuda_runtime.h>
#include <cuda_fp16.h>
#include <math.h>
#include <stdint.h>

// Problem constants
#define NB   2
#define NT   2048
#define NH   16
#define DH   64
#define DM   1024
#define ROWS 4096            // NB*NT
#define KW   512             // K=1024 packed into 512 f16x2 words

// 0.125 * log2(e): folds softmax scale + base-2 conversion into Q
#define QSCL 0.18033688011112042f

// ---------------------------------------------------------------------------
// Scratch (device globals — no allocation allowed)
// ---------------------------------------------------------------------------
__device__ float    g_cs [NT * 32 * 2];        // RoPE cos/sin table
__device__ uint32_t g_xf [ROWS * KW];          // x fp16 packed
__device__ uint32_t g_wqf[3 * DM * KW];        // w_qkv^T fp16
__device__ uint32_t g_wof[DM * KW];            // w_o^T fp16
__device__ uint32_t g_Qf [NB*NH*NT*32];        // RoPE'd Q fp16 (xQSCL)
__device__ uint32_t g_Kf [NB*NH*NT*32];        // RoPE'd K fp16
__device__ uint32_t g_Vtf[NB*NH*DH*1024];      // V^T fp16 per (b,h)
__device__ uint32_t g_atf[ROWS * KW];          // attention out fp16

// ---------------------------------------------------------------------------
// helpers
// ---------------------------------------------------------------------------
__device__ __forceinline__ uint32_t packf16(float a, float b) {   // a -> low half
    uint32_t r;
    asm("cvt.rn.f16x2.f32 %0, %1, %2;" : "=r"(r) : "f"(b), "f"(a));
    return r;
}
__device__ __forceinline__ uint32_t ex2h2(uint32_t x) {
    uint32_t y;
    asm("ex2.approx.f16x2 %0, %1;" : "=r"(y) : "r"(x));
    return y;
}
__device__ __forceinline__ void mma16f(float* c, const uint32_t* a, uint32_t b0, uint32_t b1) {
    asm volatile(
        "mma.sync.aligned.m16n8k16.row.col.f32.f16.f16.f32 "
        "{%0,%1,%2,%3}, {%4,%5,%6,%7}, {%8,%9}, {%0,%1,%2,%3};\n"
        : "+f"(c[0]), "+f"(c[1]), "+f"(c[2]), "+f"(c[3])
        : "r"(a[0]), "r"(a[1]), "r"(a[2]), "r"(a[3]), "r"(b0), "r"(b1));
}
__device__ __forceinline__ uint32_t smem_u32(const void* p) {
    uint32_t a;
    asm("{ .reg .u64 t; cvta.to.shared.u64 t, %1; cvt.u32.u64 %0, t; }" : "=r"(a) : "l"(p));
    return a;
}
__device__ __forceinline__ void ldsm4(uint32_t* r, uint32_t addr) {
    asm volatile("ldmatrix.sync.aligned.m8n8.x4.shared.b16 {%0,%1,%2,%3}, [%4];"
                 : "=r"(r[0]), "=r"(r[1]), "=r"(r[2]), "=r"(r[3]) : "r"(addr));
}
__device__ __forceinline__ void stg_cs_v2(float* p, float a, float b) {
    asm volatile("st.global.cs.v2.f32 [%0], {%1, %2};" :: "l"(p), "f"(a), "f"(b) : "memory");
}
#define CPA(dst, src) asm volatile("cp.async.cg.shared.global [%0], [%1], 16;" :: "r"(dst), "l"(src) : "memory")
#define CPC()  asm volatile("cp.async.commit_group;" ::: "memory")
#define CPW0() asm volatile("cp.async.wait_group 0;" ::: "memory")
#define CPW1() asm volatile("cp.async.wait_group 1;" ::: "memory")

// ---------------------------------------------------------------------------
// GEMM mainloop: 128x128 tile, 8 warps, fp16 single pass.
// k-chunk 64 elems, 3 rotating 36KB stages, issue-distance 2, ONE barrier
// per chunk. B-fragment loads SOFTWARE-PIPELINED (double-buffered) so the
// ldsm->mma latency of group ntp is hidden behind the MMAs of group ntp-1.
// ---------------------------------------------------------------------------
#define GST   36
#define G_ARR (128 * GST)
#define G_ARRB (G_ARR * 4)
#define G_STGB (2 * G_ARRB)      // 36864 B per stage
#define GEMM_SMEM (3 * G_STGB)   // 110592 B

#define B_ADDR(ks, ntp) \
    (((wn * 64 + (ntp) * 16 + (lane & 7) + ((lane >> 4) << 3)) * GST \
      + (ks) * 8 + (((lane >> 3) & 1) << 2)) * 4)

#define GEMM_MAINLOOP(ACC)                                                       \
    issue(0, 0); issue(1, G_STGB);                                               \
    {                                                                            \
        uint32_t cur = 0, nxt = 2 * G_STGB;                                      \
        for (int c = 0; c < 16; c++) {                                           \
            if (c < 15) { CPW1(); } else { CPW0(); }                             \
            __syncthreads();                                                     \
            if (c + 2 < 16) issue(c + 2, nxt);                                   \
            const uint32_t stb = sb + cur;                                       \
            cur += G_STGB; if (cur == 3 * G_STGB) cur = 0;                       \
            nxt += G_STGB; if (nxt == 3 * G_STGB) nxt = 0;                       \
            _Pragma("unroll")                                                    \
            for (int ks = 0; ks < 4; ks++) {                                     \
                uint32_t fh[2][4];                                               \
                _Pragma("unroll")                                                \
                for (int mt = 0; mt < 2; mt++) {                                 \
                    uint32_t ra = ((wm * 32 + mt * 16 + (lane & 15)) * GST       \
                                   + ks * 8 + ((lane >> 4) << 2)) * 4;           \
                    ldsm4(fh[mt], stb + ra);                                     \
                }                                                                \
                uint32_t bb[2][4];                                               \
                ldsm4(bb[0], stb + G_ARRB + B_ADDR(ks, 0));                      \
                _Pragma("unroll")                                                \
                for (int ntp = 0; ntp < 4; ntp++) {                              \
                    if (ntp < 3)                                                 \
                        ldsm4(bb[(ntp + 1) & 1],                                 \
                              stb + G_ARRB + B_ADDR(ks, ntp + 1));               \
                    const uint32_t* bc = bb[ntp & 1];                            \
                    _Pragma("unroll")                                            \
                    for (int s = 0; s < 2; s++) {                                \
                        _Pragma("unroll")                                        \
                        for (int mt = 0; mt < 2; mt++)                           \
                            mma16f(ACC[mt][2 * ntp + s], fh[mt],                 \
                                   bc[2 * s], bc[2 * s + 1]);                    \
                    }                                                            \
                }                                                                \
            }                                                                    \
        }                                                                        \
    }

#define GEMM_ISSUE_LAMBDA                                                        \
    const int r_ = tid >> 3, cw = (tid & 7) * 4;                                 \
    auto issue = [&](int c, uint32_t so) {                                       \
        const int k0w = c * 32;                                                  \
        _Pragma("unroll")                                                        \
        for (int a = 0; a < 2; a++) {                                            \
            _Pragma("unroll")                                                    \
            for (int i = 0; i < 4; i++) {                                        \
                int row = r_ + 32 * i;                                           \
                CPA(sb + so + a * G_ARRB + (row * GST + cw) * 4,                 \
                    srcs[a] + (size_t)row * KW + k0w + cw);                      \
            }                                                                    \
        }                                                                        \
        CPC();                                                                   \
    };

// ---------------------------------------------------------------------------
// Out-projection GEMM: f32 C epilogue (streaming stores)
// ---------------------------------------------------------------------------
__global__ __launch_bounds__(256, 2)
void gemm_f16(const uint32_t* __restrict__ A, const uint32_t* __restrict__ B,
              float* __restrict__ C, int Ntot)
{
    extern __shared__ uint32_t gsm[];
    const uint32_t sb = smem_u32(gsm);

    const int tid = threadIdx.x, lane = tid & 31, w = tid >> 5;
    const int wm = w & 3, wn = w >> 2, qq = lane & 3, g = lane >> 2;

    const uint32_t* srcs[2] = {A + (size_t)blockIdx.y * 128 * KW,
                               B + (size_t)blockIdx.x * 128 * KW};
    GEMM_ISSUE_LAMBDA

    float acc[2][8][4] = {};
    GEMM_MAINLOOP(acc)

    float* Cp = C + (size_t)blockIdx.y * 128 * Ntot + blockIdx.x * 128;
    #pragma unroll
    for (int mt = 0; mt < 2; mt++) {
        int r0 = wm * 32 + mt * 16 + g;
        #pragma unroll
        for (int nt = 0; nt < 8; nt++) {
            int c0 = wn * 64 + nt * 8 + 2 * qq;
            stg_cs_v2(Cp + (size_t)r0 * Ntot + c0,       acc[mt][nt][0], acc[mt][nt][1]);
            stg_cs_v2(Cp + (size_t)(r0 + 8) * Ntot + c0, acc[mt][nt][2], acc[mt][nt][3]);
        }
    }
}

// ---------------------------------------------------------------------------
// QKV GEMM with fused RoPE + fused V-transpose epilogue.
// bx 0..7: Q; bx 8..15: K; bx 16..23: V (transpose through smem -> V^T)
// ---------------------------------------------------------------------------
__global__ __launch_bounds__(256, 2)
void gemm_qkv(const uint32_t* __restrict__ A, const uint32_t* __restrict__ B,
              const float* __restrict__ cs,
              uint32_t* __restrict__ qf, uint32_t* __restrict__ kf,
              uint32_t* __restrict__ vtf)
{
    extern __shared__ uint32_t gsm[];
    const uint32_t sb = smem_u32(gsm);

    const int tid = threadIdx.x, lane = tid & 31, w = tid >> 5;
    const int wm = w & 3, wn = w >> 2, qq = lane & 3, g = lane >> 2;
    const int bx = blockIdx.x;

    const uint32_t* srcs[2] = {A + (size_t)blockIdx.y * 128 * KW,
                               B + (size_t)bx * 128 * KW};
    GEMM_ISSUE_LAMBDA

    float acc[2][8][4] = {};
    GEMM_MAINLOOP(acc)

    if (bx < 16) {
        const bool isQ = (bx < 8);
        uint32_t* dst = isQ ? qf : kf;
        const int h = ((bx & 7) << 1) + wn;
        const float scl = isQ ? QSCL : 1.0f;
        #pragma unroll
        for (int mt = 0; mt < 2; mt++) {
            const int rbase = blockIdx.y * 128 + wm * 32 + mt * 16 + g;
            #pragma unroll
            for (int rr = 0; rr < 2; rr++) {
                const int r = rbase + rr * 8;
                const int t = r & (NT - 1), b = r >> 11;
                const size_t wb = ((size_t)(b * NH + h) * NT + t) * 32;
                #pragma unroll
                for (int nt = 0; nt < 4; nt++) {
                    const int i0 = nt * 8 + 2 * qq;
                    float4 csv = *(const float4*)(cs + ((size_t)t * 32 + i0) * 2);
                    float lo0 = acc[mt][nt][2 * rr],     lo1 = acc[mt][nt][2 * rr + 1];
                    float hi0 = acc[mt][nt + 4][2 * rr], hi1 = acc[mt][nt + 4][2 * rr + 1];
                    float o10 = (lo0 * csv.x - hi0 * csv.y) * scl;
                    float o11 = (lo1 * csv.z - hi1 * csv.w) * scl;
                    float o20 = (hi0 * csv.x + lo0 * csv.y) * scl;
                    float o21 = (hi1 * csv.z + lo1 * csv.w) * scl;
                    const int j = nt * 4 + qq;
                    dst[wb + j]      = packf16(o10, o11);
                    dst[wb + 16 + j] = packf16(o20, o21);
                }
            }
        }
    } else {
        // V: pack fp16 into smem [128 rows][64 words + pad], transpose, write V^T
        __syncthreads();
        #pragma unroll
        for (int mt = 0; mt < 2; mt++) {
            const int r0 = wm * 32 + mt * 16 + g;
            #pragma unroll
            for (int nt = 0; nt < 8; nt++) {
                const int wd = wn * 32 + nt * 4 + qq;
                gsm[r0 * 65 + wd]       = packf16(acc[mt][nt][0], acc[mt][nt][1]);
                gsm[(r0 + 8) * 65 + wd] = packf16(acc[mt][nt][2], acc[mt][nt][3]);
            }
        }
        __syncthreads();

        const int d = tid >> 1, half = tid & 1;
        const int head = 2 * (bx - 16) + (d >> 6);
        const int dd = d & 63;
        const int rblk = blockIdx.y * 128;
        const int b = rblk >> 11, t0 = rblk & (NT - 1);
        const size_t obase = ((size_t)(b * NH + head) * DH + dd) * 1024
                             + (t0 >> 1) + half * 32;
        #pragma unroll
        for (int grp = 0; grp < 8; grp++) {
            uint32_t ow[4];
            #pragma unroll
            for (int k = 0; k < 4; k++) {
                int tw = half * 32 + grp * 4 + k;
                uint32_t w0 = gsm[(2 * tw) * 65 + (d >> 1)];
                uint32_t w1 = gsm[(2 * tw + 1) * 65 + (d >> 1)];
                ow[k] = (d & 1) ? ((w0 >> 16) | (w1 & 0xFFFF0000u))
                                : ((w0 & 0xFFFFu) | (w1 << 16));
            }
            *(uint4*)(vtf + obase + grp * 4) = *(uint4*)ow;
        }
    }
}

// ---------------------------------------------------------------------------
// Fused prep: one launch for cs table + x pack + both weight transposes.
// ---------------------------------------------------------------------------
__global__ __launch_bounds__(256)
void prep_all(const float* __restrict__ x, const float* __restrict__ wq,
              const float* __restrict__ wo, float* __restrict__ cs,
              uint32_t* __restrict__ xf, uint32_t* __restrict__ wqf,
              uint32_t* __restrict__ wof)
{
    __shared__ float sm[64][68];
    const int bx = blockIdx.x, tid = threadIdx.x;

    if (bx < 2048) {
        int e = bx * 512 + tid * 2;
        float4 v0 = *(const float4*)(x + (size_t)e * 4);
        float4 v1 = *(const float4*)(x + (size_t)e * 4 + 4);
        uint4 o;
        o.x = packf16(v0.x, v0.y); o.y = packf16(v0.z, v0.w);
        o.z = packf16(v1.x, v1.y); o.w = packf16(v1.z, v1.w);
        *(uint4*)(xf + (size_t)e * 2) = o;
        return;
    }
    if (bx < 2304) {
        int idx = (bx - 2048) * 256 + tid;
        int i = idx & 31, t = idx >> 5;
        float inv = powf(10000.0f, -(float)i / 32.0f);
        double sd, cd;
        sincos((double)((float)t * inv), &sd, &cd);
        cs[idx * 2]     = (float)cd;
        cs[idx * 2 + 1] = (float)sd;
        return;
    }

    const float* W;
    uint32_t* wtf;
    int N, bb;
    if (bx < 3072) { W = wq; wtf = wqf; N = 3 * DM; bb = bx - 2304; }
    else           { W = wo; wtf = wof; N = DM;     bb = bx - 3072; }
    const int nblk = N / 64;
    const int n0 = (bb % nblk) * 64, k0 = (bb / nblk) * 64;

    #pragma unroll
    for (int i = 0; i < 4; i++) {
        int e = tid + 256 * i;
        int kr = e >> 4, c4 = (e & 15) * 4;
        *(float4*)&sm[kr][c4] = *(const float4*)(W + (size_t)(k0 + kr) * N + n0 + c4);
    }
    __syncthreads();
    const int n = tid >> 2, qq = tid & 3;
    uint32_t ow[8];
    #pragma unroll
    for (int wi = 0; wi < 8; wi++) {
        int wd = qq * 8 + wi;
        ow[wi] = packf16(sm[2 * wd][n], sm[2 * wd + 1][n]);
    }
    size_t o = (size_t)(n0 + n) * KW + (k0 >> 1) + qq * 8;
    *(uint4*)(wtf + o)     = *(uint4*)&ow[0];
    *(uint4*)(wtf + o + 4) = *(uint4*)&ow[4];
}

// ---------------------------------------------------------------------------
// Flash attention: fp16 MMA, register P, ZERO-OFFSET softmax, ones-MMA
// row sums; KV tile 128 (two halves), 3 rotating buffers, 1 barrier/tile.
// (unchanged from round 16)
// ---------------------------------------------------------------------------
#define ATP 36
#define AT_BUF_W 9216
#define AT_SMEM_W (3 * AT_BUF_W)     // 110592 B
#define ONES2 0x3C003C00u

__global__ __launch_bounds__(256, 2)
void attn_f16r(const uint32_t* __restrict__ Qf, const uint32_t* __restrict__ Kf,
               const uint32_t* __restrict__ Vtf, uint32_t* __restrict__ Of)
{
    extern __shared__ uint32_t smw[];
    const uint32_t sb = smem_u32(smw);

    const int tid = threadIdx.x, lane = tid & 31, w = tid >> 5;
    const int g = lane >> 2, qq = lane & 3;
    const int qtile = blockIdx.x, bh = blockIdx.y;
    const int pr0 = w * 16 + g;

    const size_t qrow0 = (size_t)bh * NT + qtile * 128;

    const int le = tid;
    const int r0a = le >> 3, c0a = (le & 7) * 4;
    const int r0b = r0a + 32, r0c = r0a + 64, r0d = r0a + 96;
    const uint32_t* Kbase = Kf + ((size_t)bh * NT) * 32 + c0a;
    const uint32_t* Vbase = Vtf + ((size_t)bh * DH) * 1024 + c0a;

    auto issueKV = [&](int kt, uint32_t bo) {
        const int rows[4] = {r0a, r0b, r0c, r0d};
        #pragma unroll
        for (int i = 0; i < 4; i++) {
            int r = rows[i];
            int kh = r >> 6, rk = r & 63;
            CPA(sb + (bo + kh * 2304 + rk * ATP + c0a) * 4,
                Kbase + (size_t)(kt * 128 + r) * 32);
            CPA(sb + (bo + 4608 + kh * 2304 + rk * ATP + c0a) * 4,
                Vbase + (size_t)rk * 1024 + kt * 64 + kh * 32);
        }
        CPC();
    };

    issueKV(0, 0);
    issueKV(1, AT_BUF_W);

    uint32_t qfr[4][4];
    {
        const uint32_t* Qr0 = Qf + (qrow0 + pr0) * 32;
        const uint32_t* Qr8 = Qf + (qrow0 + pr0 + 8) * 32;
        #pragma unroll
        for (int kc = 0; kc < 4; kc++) {
            qfr[kc][0] = Qr0[8 * kc + qq];
            qfr[kc][1] = Qr8[8 * kc + qq];
            qfr[kc][2] = Qr0[8 * kc + qq + 4];
            qfr[kc][3] = Qr8[8 * kc + qq + 4];
        }
    }

    float of[8][4] = {};
    float l0 = 0.0f, l1 = 0.0f;

    uint32_t cur = 0, nxt = 2 * AT_BUF_W;
    for (int kt = 0; kt < 16; kt++) {
        if (kt < 15) { CPW1(); } else { CPW0(); }
        __syncthreads();
        if (kt + 2 < 16) issueKV(kt + 2, nxt);
        const uint32_t bo = cur;
        cur = cur + AT_BUF_W; if (cur == 3 * AT_BUF_W) cur = 0;
        nxt = nxt + AT_BUF_W; if (nxt == 3 * AT_BUF_W) nxt = 0;

        #pragma unroll
        for (int half = 0; half < 2; half++) {
            const uint32_t kb4 = (bo + half * 2304) * 4;
            const uint32_t vb4 = (bo + 4608 + half * 2304) * 4;

            float sf[8][4] = {};
            #pragma unroll
            for (int kc = 0; kc < 4; kc++) {
                #pragma unroll
                for (int ntp = 0; ntp < 4; ntp++) {
                    uint32_t rb = ((ntp * 16 + (lane & 7) + ((lane >> 4) << 3)) * ATP
                                   + kc * 8 + (((lane >> 3) & 1) << 2)) * 4;
                    uint32_t bb[4];
                    ldsm4(bb, sb + kb4 + rb);
                    mma16f(sf[2 * ntp + 0], qfr[kc], bb[0], bb[1]);
                    mma16f(sf[2 * ntp + 1], qfr[kc], bb[2], bb[3]);
                }
            }

            float rsacc[4] = {};
            #pragma unroll
            for (int jc = 0; jc < 4; jc++) {
                uint32_t pa[4];
                pa[0] = ex2h2(packf16(sf[2 * jc][0],     sf[2 * jc][1]));
                pa[1] = ex2h2(packf16(sf[2 * jc][2],     sf[2 * jc][3]));
                pa[2] = ex2h2(packf16(sf[2 * jc + 1][0], sf[2 * jc + 1][1]));
                pa[3] = ex2h2(packf16(sf[2 * jc + 1][2], sf[2 * jc + 1][3]));
                mma16f(rsacc, pa, ONES2, ONES2);
                #pragma unroll
                for (int ntp = 0; ntp < 4; ntp++) {
                    uint32_t rb = ((ntp * 16 + (lane & 7) + ((lane >> 4) << 3)) * ATP
                                   + jc * 8 + (((lane >> 3) & 1) << 2)) * 4;
                    uint32_t bb[4];
                    ldsm4(bb, sb + vb4 + rb);
                    mma16f(of[2 * ntp + 0], pa, bb[0], bb[1]);
                    mma16f(of[2 * ntp + 1], pa, bb[2], bb[3]);
                }
            }
            l0 += rsacc[0];
            l1 += rsacc[2];
        }
    }

    const float inv0 = 1.0f / l0, inv1 = 1.0f / l1;
    const int b = bh >> 4, hh = bh & 15;
    const size_t row0 = (size_t)b * NT + qtile * 128 + pr0;
    #pragma unroll
    for (int nt = 0; nt < 8; nt++) {
        int wc = hh * 32 + nt * 4 + qq;
        Of[row0 * KW + wc]       = packf16(of[nt][0] * inv0, of[nt][1] * inv0);
        Of[(row0 + 8) * KW + wc] = packf16(of[nt][2] * inv1, of[nt][3] * inv1);
    }
}

// ---------------------------------------------------------------------------
extern "C" void kernel_launch(void* const* d_in, const int* in_sizes, int n_in,
                              void* d_out, int out_size)
{
    const float* x     = (const float*)d_in[0];
    const float* w_qkv = (const float*)d_in[1];
    const float* w_o   = (const float*)d_in[2];
    for (int i = 0; i < n_in; i++) {
        if (in_sizes[i] == ROWS * DM)        x     = (const float*)d_in[i];
        else if (in_sizes[i] == DM * 3 * DM) w_qkv = (const float*)d_in[i];
        else if (in_sizes[i] == DM * DM)     w_o   = (const float*)d_in[i];
    }
    float* out = (float*)d_out;
    (void)out_size;

    float *cs;
    uint32_t *xf, *wqf, *wof, *Qfp, *Kfp, *Vtf, *atf;
    cudaGetSymbolAddress((void**)&cs,  g_cs);
    cudaGetSymbolAddress((void**)&xf,  g_xf);
    cudaGetSymbolAddress((void**)&wqf, g_wqf);
    cudaGetSymbolAddress((void**)&wof, g_wof);
    cudaGetSymbolAddress((void**)&Qfp, g_Qf);
    cudaGetSymbolAddress((void**)&Kfp, g_Kf);
    cudaGetSymbolAddress((void**)&Vtf, g_Vtf);
    cudaGetSymbolAddress((void**)&atf, g_atf);

    // 0) Fused prep (single launch)
    prep_all<<<3328, 256>>>(x, w_qkv, w_o, cs, xf, wqf, wof);

    // 1) QKV projection with fused RoPE + fused V-transpose epilogue
    cudaFuncSetAttribute(gemm_qkv, cudaFuncAttributeMaxDynamicSharedMemorySize, GEMM_SMEM);
    gemm_qkv<<<dim3(3 * DM / 128, ROWS / 128), 256, GEMM_SMEM>>>(xf, wqf, cs, Qfp, Kfp, Vtf);

    // 2) Attention (zero-offset softmax)
    cudaFuncSetAttribute(attn_f16r, cudaFuncAttributeMaxDynamicSharedMemorySize, AT_SMEM_W * 4);
    attn_f16r<<<dim3(NT / 128, NB * NH), 256, AT_SMEM_W * 4>>>(Qfp, Kfp, Vtf, atf);

    // 3) Output projection
    cudaFuncSetAttribute(gemm_f16, cudaFuncAttributeMaxDynamicSharedMemorySize, GEMM_SMEM);
    gemm_f16<<<dim3(DM / 128, ROWS / 128), 256, GEMM_SMEM>>>(atf, wof, out, DM);
}